// round 17
// baseline (speedup 1.0000x reference)
#include <cuda_runtime.h>
#include <cuda_fp16.h>

// QuantizedBatchNorm3d: x [8,64,32,64,64] fp32, weight[64], bias[64] -> y same shape.
// fake_quant(exp=5, sig=10, RNE) == IEEE fp16 round-trip for all reachable values.
//
// R17: warp-autonomous fused pipeline. NO __syncthreads in the main loops.
// Warps pull 1024-float4 tiles from global ticket counters (phase 1 ascending,
// phase 2 exact-reverse for L2 frontier harvest). Phase 1: 8-deep front-batched
// loads, per-warp partial -> fixed slot, acq_rel channel counter; 256th arrival
// finalizes params (fixed-order, deterministic) and release-publishes a flag.
// Phase 2: flag spin only on channel change (params cached in regs), __ldcg
// param reads, __ldcs/__stcs streams. Work-stealing is deadlock-free under any
// residency; last-exiting block resets all state for graph replays.

#define NC    64
#define CPC   (1 << 20)              // elements per channel
#define NTHR  256
#define NWT   16384                  // warp-tiles of 1024 float4 (16KB)
#define WPC   256                    // warp-tiles per channel

__device__ float    g_wsum[NWT];
__device__ float    g_wsq [NWT];
__device__ float4   g_params[NC];
__device__ unsigned g_tick1, g_tick2, g_fin;   // zero-init; self-resetting
__device__ unsigned g_cnt [NC];
__device__ unsigned g_flag[NC];

__device__ __forceinline__ float fq1(float v) {
    return __half2float(__float2half_rn(v));
}
__device__ __forceinline__ float2 fq2(float a, float b) {
    __half2 h = __floats2half2_rn(a, b);
    return __half22float2(h);
}
__device__ __forceinline__ size_t wt_base(int T) {
    const int c = T >> 8, r = T & 255;          // 256 tiles per channel
    return ((size_t)((r >> 5) * NC + c) << 15)  // (n, c) slice
         + ((size_t)(r & 31) << 10);            // 1024-f4 tile within slice
}

__global__ void __launch_bounds__(NTHR)
qbn_fused(const float* __restrict__ x,
          const float* __restrict__ weight,
          const float* __restrict__ bias,
          float* __restrict__ out) {
    const int t = threadIdx.x, lane = t & 31;
    const float4* x4 = reinterpret_cast<const float4*>(x);
    float4*       o4 = reinterpret_cast<float4*>(out);

    // ---------------- Phase 1: warp-ticket reduce sweep (ascending) ----------------
    for (;;) {
        unsigned T = 0;
        if (lane == 0) T = atomicAdd(&g_tick1, 1u);
        T = __shfl_sync(0xffffffffu, T, 0);
        if (T >= NWT) break;
        const int c = (int)(T >> 8);
        const size_t base = wt_base((int)T);

        float s = 0.f, sq = 0.f;
        #pragma unroll 1
        for (int g = 0; g < 4; g++) {
            float4 v[8];
            #pragma unroll
            for (int j = 0; j < 8; j++)
                v[j] = x4[base + (size_t)(g * 8 + j) * 32 + lane];
            #pragma unroll
            for (int j = 0; j < 8; j++) {
                float2 a = fq2(v[j].x, v[j].y), d = fq2(v[j].z, v[j].w);
                s  += (a.x + a.y) + (d.x + d.y);
                sq += a.x*a.x + a.y*a.y + d.x*d.x + d.y*d.y;
            }
        }
        #pragma unroll
        for (int o = 16; o > 0; o >>= 1) {
            s  += __shfl_down_sync(0xffffffffu, s,  o);
            sq += __shfl_down_sync(0xffffffffu, sq, o);
        }
        unsigned old = 0;
        if (lane == 0) {
            g_wsum[T] = s;
            g_wsq [T] = sq;
            asm volatile("atom.acq_rel.gpu.global.add.u32 %0, [%1], %2;"
                         : "=r"(old) : "l"(&g_cnt[c]), "r"(1u) : "memory");
        }
        old = __shfl_sync(0xffffffffu, old, 0);

        if (old == WPC - 1) {          // this warp completes channel c: finalize
            float ss = 0.f, qq = 0.f;
            #pragma unroll
            for (int i = 0; i < 8; i++) {      // fixed order -> deterministic
                ss += __ldcg(&g_wsum[c * WPC + lane * 8 + i]);
                qq += __ldcg(&g_wsq [c * WPC + lane * 8 + i]);
            }
            #pragma unroll
            for (int o = 16; o > 0; o >>= 1) {
                ss += __shfl_down_sync(0xffffffffu, ss, o);
                qq += __shfl_down_sync(0xffffffffu, qq, o);
            }
            if (lane == 0) {
                const float inv_n = 1.0f / (float)CPC;
                float mean = ss * inv_n;
                float var  = qq * inv_n - mean * mean;
                float mean_q  = fq1(mean);
                float var_q   = fq1(var);
                float inv_std = 1.0f / sqrtf(var_q + 1e-5f);
                g_params[c] = make_float4(mean_q, inv_std,
                                          fq1(weight[c]), fq1(bias[c]));
                asm volatile("st.release.gpu.global.u32 [%0], %1;"
                             :: "l"(&g_flag[c]), "r"(1u) : "memory");
            }
        }
    }

    // ------------- Phase 2: warp-ticket apply sweep (exact reverse) -------------
    int cprev = -1;
    float4 p = make_float4(0.f, 0.f, 0.f, 0.f);
    for (;;) {
        unsigned U = 0;
        if (lane == 0) U = atomicAdd(&g_tick2, 1u);
        U = __shfl_sync(0xffffffffu, U, 0);
        if (U >= NWT) break;
        const int T = (NWT - 1) - (int)U;       // reverse: freshest L2 first
        const int c = T >> 8;
        const size_t base = wt_base(T);

        if (c != cprev) {                       // spin only on channel change
            if (lane == 0) {
                unsigned f;
                for (;;) {
                    asm volatile("ld.acquire.gpu.global.u32 %0, [%1];"
                                 : "=r"(f) : "l"(&g_flag[c]) : "memory");
                    if (f) break;
                    __nanosleep(64);
                }
            }
            __syncwarp();
            p = __ldcg(&g_params[c]);           // L2-coherent, post-flag
            cprev = c;
        }

        #pragma unroll 1
        for (int g = 0; g < 4; g++) {
            float4 v[8];
            #pragma unroll
            for (int j = 0; j < 8; j++)
                v[j] = __ldcs(x4 + base + (size_t)(g * 8 + j) * 32 + lane);
            #pragma unroll
            for (int j = 0; j < 8; j++) {
                float2 a = fq2(v[j].x, v[j].y), d = fq2(v[j].z, v[j].w);
                float y0 = fmaf(p.z, (a.x - p.x) * p.y, p.w);
                float y1 = fmaf(p.z, (a.y - p.x) * p.y, p.w);
                float y2 = fmaf(p.z, (d.x - p.x) * p.y, p.w);
                float y3 = fmaf(p.z, (d.y - p.x) * p.y, p.w);
                float2 q0 = fq2(y0, y1), q1 = fq2(y2, y3);
                __stcs(o4 + base + (size_t)(g * 8 + j) * 32 + lane,
                       make_float4(q0.x, q0.y, q1.x, q1.y));
            }
        }
    }

    // -------- Exit: last block (all work finished everywhere) resets state --------
    __syncthreads();
    if (t == 0) {
        unsigned old = atomicAdd(&g_fin, 1u);
        if (old == gridDim.x - 1) {
            g_tick1 = 0u; g_tick2 = 0u; g_fin = 0u;
            #pragma unroll
            for (int i = 0; i < NC; i++) { g_cnt[i] = 0u; g_flag[i] = 0u; }
        }
    }
}

extern "C" void kernel_launch(void* const* d_in, const int* in_sizes, int n_in,
                              void* d_out, int out_size) {
    const float* x      = (const float*)d_in[0];
    const float* weight = (const float*)d_in[1];
    const float* bias   = (const float*)d_in[2];
    float* out = (float*)d_out;

    static int nblocks = 0;
    if (nblocks == 0) {
        int sms = 0;
        cudaDeviceGetAttribute(&sms, cudaDevAttrMultiProcessorCount, 0);
        nblocks = 6 * sms;     // >= resident capacity; extras exit via empty tickets
    }
    qbn_fused<<<nblocks, NTHR>>>(x, weight, bias, out);
}